// round 7
// baseline (speedup 1.0000x reference)
#include <cuda_runtime.h>
#include <cuda_fp16.h>

#define N_USERS 100000
#define N_ITEMS 200000
#define N_NODES (N_USERS + N_ITEMS)
#define NNZ     9600000
#define DIM     64
#define TOTAL   ((size_t)N_NODES * DIM)
#define TOTAL4  (TOTAL / 4)
#define CAP     128                     // slots/row; mean degree 32, ~17 sigma

// Scratch (__device__ globals, alloc-free rule).
// h0 = fp16(e0), h1 = e1, h2 = e2. Final combine reads input fp32 directly.
__device__ __align__(16) __half g_h0[TOTAL];
__device__ __align__(16) __half g_h1[TOTAL];
__device__ __align__(16) __half g_h2[TOTAL];
__device__ __align__(16) int2   g_bucket[(size_t)N_NODES * CAP];
__device__ int g_cnt[N_NODES];

// ---------------------------------------------------------------------------
// init: g_h0 = fp16(concat(user,item)); g_cnt = 0. (No acc writes anymore.)
// ---------------------------------------------------------------------------
__global__ __launch_bounds__(256) void init_kernel(
    const float* __restrict__ user_emb,
    const float* __restrict__ item_emb)
{
    size_t i = (size_t)blockIdx.x * blockDim.x + threadIdx.x;
    if (i < N_NODES) g_cnt[i] = 0;
    if (i >= TOTAL4) return;
    const size_t ub = (size_t)N_USERS * DIM / 4;
    float4 v = (i < ub) ? ((const float4*)user_emb)[i]
                        : ((const float4*)item_emb)[i - ub];
    uint2 h;
    __half2 h01 = __floats2half2_rn(v.x, v.y);
    __half2 h23 = __floats2half2_rn(v.z, v.w);
    h.x = *(unsigned*)&h01;
    h.y = *(unsigned*)&h23;
    ((uint2*)g_h0)[i] = h;
}

// ---------------------------------------------------------------------------
// Single-pass bucketing: pos = cnt[r]++ ; bucket[r][pos] = (col, val).
// ---------------------------------------------------------------------------
__global__ __launch_bounds__(256) void bucket_kernel(
    const int*   __restrict__ rows,
    const int*   __restrict__ cols,
    const float* __restrict__ vals)
{
    int e = blockIdx.x * blockDim.x + threadIdx.x;
    if (e >= NNZ) return;
    int r = __ldcs(rows + e);
    int pos = atomicAdd(&g_cnt[r], 1);
    if (pos < CAP)
        g_bucket[(size_t)r * CAP + pos] =
            make_int2(__ldcs(cols + e), __float_as_int(__ldcs(vals + e)));
}

// ---------------------------------------------------------------------------
// SpMM: warp-per-row. Lane-parallel meta load (coalesced, one int2 per lane)
// + shfl broadcast -> gathers are independent back-to-back LDGs.
// Lane owns 2 dims (half2 gather, fp32 accumulate). Writes fp16 dst only.
// ---------------------------------------------------------------------------
__device__ __forceinline__ float2 row_segsum(
    const __half* __restrict__ src, int row, int lane)
{
    int cnt = __ldg(&g_cnt[row]);
    if (cnt > CAP) cnt = CAP;
    const int2* ep = g_bucket + (size_t)row * CAP;

    float2 sum = make_float2(0.f, 0.f);
    for (int base = 0; base < cnt; base += 32) {
        int m = cnt - base; if (m > 32) m = 32;
        int2 meta = make_int2(0, 0);
        if (lane < m) meta = __ldg(ep + base + lane);
        for (int j = 0; j < m; j++) {
            int   col = __shfl_sync(0xffffffffu, meta.x, j);
            float v   = __int_as_float(__shfl_sync(0xffffffffu, meta.y, j));
            __half2 x = __ldg((const __half2*)(src + (size_t)col * DIM) + lane);
            float2 f = __half22float2(x);
            sum.x = fmaf(f.x, v, sum.x);
            sum.y = fmaf(f.y, v, sum.y);
        }
    }
    return sum;
}

__global__ __launch_bounds__(256) void spmm_kernel(
    const __half* __restrict__ src,
    __half*       __restrict__ dst)
{
    int warp = (blockIdx.x * blockDim.x + threadIdx.x) >> 5;
    int lane = threadIdx.x & 31;
    if (warp >= N_NODES) return;
    float2 sum = row_segsum(src, warp, lane);
    ((__half2*)dst)[(size_t)warp * (DIM / 2) + lane] =
        __floats2half2_rn(sum.x, sum.y);
}

// Layer 3 + final combine: out = (input_f32 + e1 + e2 + sum3) * 0.25
__global__ __launch_bounds__(256) void spmm_final_kernel(
    const __half* __restrict__ src,        // h2 (e2): gather source
    const float*  __restrict__ user_emb,
    const float*  __restrict__ item_emb,
    float*        __restrict__ out)
{
    int warp = (blockIdx.x * blockDim.x + threadIdx.x) >> 5;
    int lane = threadIdx.x & 31;
    if (warp >= N_NODES) return;
    float2 sum = row_segsum(src, warp, lane);

    size_t o = (size_t)warp * (DIM / 2) + lane;
    float2 e1 = __half22float2(((const __half2*)g_h1)[o]);
    float2 e2 = __half22float2(((const __half2*)g_h2)[o]);
    const float* inp = (warp < N_USERS)
        ? user_emb + (size_t)warp * DIM
        : item_emb + (size_t)(warp - N_USERS) * DIM;
    float2 e0 = ((const float2*)inp)[lane];

    float2 r;
    r.x = (e0.x + e1.x + e2.x + sum.x) * 0.25f;
    r.y = (e0.y + e1.y + e2.y + sum.y) * 0.25f;
    ((float2*)out)[o] = r;
}

extern "C" void kernel_launch(void* const* d_in, const int* in_sizes, int n_in,
                              void* d_out, int out_size)
{
    const int*   rows     = (const int*)  d_in[0];
    const int*   cols     = (const int*)  d_in[1];
    const float* vals     = (const float*)d_in[2];
    const float* user_emb = (const float*)d_in[3];
    const float* item_emb = (const float*)d_in[4];
    float*       out      = (float*)d_out;

    __half *h0, *h1, *h2;
    cudaGetSymbolAddress((void**)&h0, g_h0);
    cudaGetSymbolAddress((void**)&h1, g_h1);
    cudaGetSymbolAddress((void**)&h2, g_h2);

    const int thr = 256;
    const int edge_blocks = (NNZ + thr - 1) / thr;
    const int vec_blocks  = (int)((TOTAL4 + thr - 1) / thr);
    const int spmm_blocks = (int)(((long long)N_NODES * 32 + thr - 1) / thr);

    init_kernel<<<vec_blocks, thr>>>(user_emb, item_emb);
    bucket_kernel<<<edge_blocks, thr>>>(rows, cols, vals);

    spmm_kernel<<<spmm_blocks, thr>>>(h0, h1);              // e1 = A e0
    spmm_kernel<<<spmm_blocks, thr>>>(h1, h2);              // e2 = A e1
    spmm_final_kernel<<<spmm_blocks, thr>>>(h2, user_emb, item_emb, out);
}

// round 8
// speedup vs baseline: 1.4163x; 1.4163x over previous
#include <cuda_runtime.h>
#include <cuda_fp16.h>

#define N_USERS 100000
#define N_ITEMS 200000
#define N_NODES (N_USERS + N_ITEMS)
#define NNZ     9600000
#define DIM     64
#define TOTAL   ((size_t)N_NODES * DIM)
#define TOTAL4  (TOTAL / 4)
#define CAP     128                     // slots/row; mean degree 32, ~17 sigma

// Scratch (__device__ globals, alloc-free rule).
// h0 = fp16(e0), h1 = e1, h2 = e2. Final combine reads fp32 inputs directly.
__device__ __align__(16) __half g_h0[TOTAL];
__device__ __align__(16) __half g_h1[TOTAL];
__device__ __align__(16) __half g_h2[TOTAL];
__device__ __align__(16) int2   g_bucket[(size_t)N_NODES * CAP];
__device__ int g_cnt[N_NODES];

// ---------------------------------------------------------------------------
// init: g_h0 = fp16(concat(user,item)); g_cnt = 0.
// ---------------------------------------------------------------------------
__global__ __launch_bounds__(256) void init_kernel(
    const float* __restrict__ user_emb,
    const float* __restrict__ item_emb)
{
    size_t i = (size_t)blockIdx.x * blockDim.x + threadIdx.x;
    if (i < N_NODES) g_cnt[i] = 0;
    if (i >= TOTAL4) return;
    const size_t ub = (size_t)N_USERS * DIM / 4;
    float4 v = (i < ub) ? ((const float4*)user_emb)[i]
                        : ((const float4*)item_emb)[i - ub];
    uint2 h;
    __half2 h01 = __floats2half2_rn(v.x, v.y);
    __half2 h23 = __floats2half2_rn(v.z, v.w);
    h.x = *(unsigned*)&h01;
    h.y = *(unsigned*)&h23;
    ((uint2*)g_h0)[i] = h;
}

// ---------------------------------------------------------------------------
// Single-pass bucketing: pos = cnt[r]++ ; bucket[r][pos] = (col, val).
// ---------------------------------------------------------------------------
__global__ __launch_bounds__(256) void bucket_kernel(
    const int*   __restrict__ rows,
    const int*   __restrict__ cols,
    const float* __restrict__ vals)
{
    int e = blockIdx.x * blockDim.x + threadIdx.x;
    if (e >= NNZ) return;
    int r = __ldcs(rows + e);
    int pos = atomicAdd(&g_cnt[r], 1);
    if (pos < CAP)
        g_bucket[(size_t)r * CAP + pos] =
            make_int2(__ldcs(cols + e), __float_as_int(__ldcs(vals + e)));
}

// ---------------------------------------------------------------------------
// Warp-per-row segment sum, R6-style meta (int4 = 2 edges per broadcast load),
// unrolled to 4 edges/iteration for MLP (2 meta loads + 4 gathers in flight).
// Lane owns 2 dims: half2 gather, fp32 accumulate.
// ---------------------------------------------------------------------------
__device__ __forceinline__ float2 row_segsum(
    const __half* __restrict__ src, int row, int lane)
{
    int cnt = __ldg(&g_cnt[row]);
    if (cnt > CAP) cnt = CAP;
    const int2* ep = g_bucket + (size_t)row * CAP;

    float2 sum = make_float2(0.f, 0.f);
    int i = 0;
    for (; i + 3 < cnt; i += 4) {
        int4 ea = __ldg((const int4*)(ep + i));        // edges i, i+1
        int4 eb = __ldg((const int4*)(ep + i + 2));    // edges i+2, i+3
        __half2 x0 = __ldg((const __half2*)(src + (size_t)ea.x * DIM) + lane);
        __half2 x1 = __ldg((const __half2*)(src + (size_t)ea.z * DIM) + lane);
        __half2 x2 = __ldg((const __half2*)(src + (size_t)eb.x * DIM) + lane);
        __half2 x3 = __ldg((const __half2*)(src + (size_t)eb.z * DIM) + lane);
        float v0 = __int_as_float(ea.y);
        float v1 = __int_as_float(ea.w);
        float v2 = __int_as_float(eb.y);
        float v3 = __int_as_float(eb.w);
        float2 f0 = __half22float2(x0);
        float2 f1 = __half22float2(x1);
        float2 f2 = __half22float2(x2);
        float2 f3 = __half22float2(x3);
        sum.x = fmaf(f0.x, v0, sum.x); sum.y = fmaf(f0.y, v0, sum.y);
        sum.x = fmaf(f1.x, v1, sum.x); sum.y = fmaf(f1.y, v1, sum.y);
        sum.x = fmaf(f2.x, v2, sum.x); sum.y = fmaf(f2.y, v2, sum.y);
        sum.x = fmaf(f3.x, v3, sum.x); sum.y = fmaf(f3.y, v3, sum.y);
    }
    for (; i < cnt; i++) {                             // tail (<=3)
        int2 ev = __ldg(ep + i);
        float v = __int_as_float(ev.y);
        __half2 x = __ldg((const __half2*)(src + (size_t)ev.x * DIM) + lane);
        float2 f = __half22float2(x);
        sum.x = fmaf(f.x, v, sum.x);
        sum.y = fmaf(f.y, v, sum.y);
    }
    return sum;
}

__global__ __launch_bounds__(256) void spmm_kernel(
    const __half* __restrict__ src,
    __half*       __restrict__ dst)
{
    int warp = (blockIdx.x * blockDim.x + threadIdx.x) >> 5;
    int lane = threadIdx.x & 31;
    if (warp >= N_NODES) return;
    float2 sum = row_segsum(src, warp, lane);
    ((__half2*)dst)[(size_t)warp * (DIM / 2) + lane] =
        __floats2half2_rn(sum.x, sum.y);
}

// Layer 3 + final combine: out = (e0_f32 + e1 + e2 + sum3) * 0.25
__global__ __launch_bounds__(256) void spmm_final_kernel(
    const __half* __restrict__ src,        // h2 (e2): gather source
    const float*  __restrict__ user_emb,
    const float*  __restrict__ item_emb,
    float*        __restrict__ out)
{
    int warp = (blockIdx.x * blockDim.x + threadIdx.x) >> 5;
    int lane = threadIdx.x & 31;
    if (warp >= N_NODES) return;
    float2 sum = row_segsum(src, warp, lane);

    size_t o = (size_t)warp * (DIM / 2) + lane;
    float2 e1 = __half22float2(__ldg((const __half2*)g_h1 + o));
    float2 e2 = __half22float2(__ldg((const __half2*)g_h2 + o));
    const float* inp = (warp < N_USERS)
        ? user_emb + (size_t)warp * DIM
        : item_emb + (size_t)(warp - N_USERS) * DIM;
    float2 e0 = __ldg((const float2*)inp + lane);

    float2 r;
    r.x = (e0.x + e1.x + e2.x + sum.x) * 0.25f;
    r.y = (e0.y + e1.y + e2.y + sum.y) * 0.25f;
    ((float2*)out)[o] = r;
}

extern "C" void kernel_launch(void* const* d_in, const int* in_sizes, int n_in,
                              void* d_out, int out_size)
{
    const int*   rows     = (const int*)  d_in[0];
    const int*   cols     = (const int*)  d_in[1];
    const float* vals     = (const float*)d_in[2];
    const float* user_emb = (const float*)d_in[3];
    const float* item_emb = (const float*)d_in[4];
    float*       out      = (float*)d_out;

    __half *h0, *h1, *h2;
    cudaGetSymbolAddress((void**)&h0, g_h0);
    cudaGetSymbolAddress((void**)&h1, g_h1);
    cudaGetSymbolAddress((void**)&h2, g_h2);

    const int thr = 256;
    const int edge_blocks = (NNZ + thr - 1) / thr;
    const int vec_blocks  = (int)((TOTAL4 + thr - 1) / thr);
    const int spmm_blocks = (int)(((long long)N_NODES * 32 + thr - 1) / thr);

    init_kernel<<<vec_blocks, thr>>>(user_emb, item_emb);
    bucket_kernel<<<edge_blocks, thr>>>(rows, cols, vals);

    spmm_kernel<<<spmm_blocks, thr>>>(h0, h1);              // e1 = A e0
    spmm_kernel<<<spmm_blocks, thr>>>(h1, h2);              // e2 = A e1
    spmm_final_kernel<<<spmm_blocks, thr>>>(h2, user_emb, item_emb, out);
}